// round 15
// baseline (speedup 1.0000x reference)
#include <cuda_runtime.h>
#include <math.h>

#define B 32
#define NN 128
#define C 128
#define HE 64
#define NH 256
#define OUT 10
#define EPS_BN 1e-5f

// ---------------- scratch (device globals; no allocs allowed) ----------------
__device__ float g_u[B*NN*HE];
__device__ float g_v[B*NN*HE];
__device__ float g_s[B*NN*NN];
__device__ float g_L0[B*NN*NN];
__device__ float g_L1[B*NN*NN];
__device__ float g_M0[B*NN*NN];
__device__ float g_M1[B*NN*NN];
__device__ float g_Xcat[B*NN*1536];   // max 6*256 wide
__device__ float g_h0[B*NN*512];
__device__ float g_h1[B*NN*512];
__device__ float g_pool[B*512];
__device__ float g_fc1[B*NH];

__device__ __forceinline__ unsigned f2tf(float f) {
    unsigned u;
    asm("cvt.rna.tf32.f32 %0, %1;" : "=r"(u) : "f"(f));
    return u;
}
__device__ __forceinline__ uint4 f2tf4(float4 v) {
    uint4 s; s.x = f2tf(v.x); s.y = f2tf(v.y); s.z = f2tf(v.z); s.w = f2tf(v.w);
    return s;
}

__device__ __forceinline__ void mma_tf32(float c[4], const unsigned a[4], const unsigned b[2]) {
    asm volatile(
        "mma.sync.aligned.m16n8k8.row.col.f32.tf32.tf32.f32 "
        "{%0,%1,%2,%3}, {%4,%5,%6,%7}, {%8,%9}, {%0,%1,%2,%3};"
        : "+f"(c[0]), "+f"(c[1]), "+f"(c[2]), "+f"(c[3])
        : "r"(a[0]), "r"(a[1]), "r"(a[2]), "r"(a[3]), "r"(b[0]), "r"(b[1]));
}

// ---------------- edge MLP: u = x@eW1[:C]+eb1, v = x@eW1[C:] ----------------
__global__ void k_uv(const float* __restrict__ x, const float* __restrict__ eW1,
                     const float* __restrict__ eb1) {
    int row = blockIdx.x;            // b*NN + n
    __shared__ float xs[C];
    for (int c = threadIdx.x; c < C; c += blockDim.x) xs[c] = x[row*C + c];
    __syncthreads();
    int t = threadIdx.x;             // 64 threads = HE
    float u = 0.f, v = 0.f;
#pragma unroll 4
    for (int c = 0; c < C; c++) {
        float xv = xs[c];
        u += xv * eW1[c*HE + t];
        v += xv * eW1[(C + c)*HE + t];
    }
    g_u[row*HE + t] = u + eb1[t];
    g_v[row*HE + t] = v;
}

// ---------------- edge scores s[b,i,j] ----------------
#define IC 16
__global__ void k_score(const float* __restrict__ eW2, const float* __restrict__ eb2) {
    int b  = blockIdx.x / (NN / IC);
    int i0 = (blockIdx.x % (NN / IC)) * IC;
    __shared__ float vs[NN*(HE + 1)];
    __shared__ float us[IC*HE];
    __shared__ float w2[HE];
    int tid = threadIdx.x;           // 128
    for (int idx = tid; idx < NN*HE; idx += 128) {
        int j = idx / HE, h = idx % HE;
        vs[j*(HE + 1) + h] = g_v[(b*NN + j)*HE + h];
    }
    for (int idx = tid; idx < IC*HE; idx += 128)
        us[idx] = g_u[(b*NN + i0)*HE + idx];
    if (tid < HE) w2[tid] = eW2[tid];
    __syncthreads();
    float e2 = eb2[0];
    int j = tid;
    for (int ii = 0; ii < IC; ii++) {
        float acc = e2;
#pragma unroll 8
        for (int h = 0; h < HE; h++) {
            float t = us[ii*HE + h] + vs[j*(HE + 1) + h];
            acc += w2[h] * fmaxf(t, 0.f);
        }
        g_s[(b*NN + i0 + ii)*NN + j] = acc;
    }
}

// ====== fused adjacency: blocks 0..31 -> L0 from A; 32..63 -> L1 from s ======
__global__ void k_adj(const float* __restrict__ A, const float* __restrict__ mask,
                      float* __restrict__ L0, float* __restrict__ L1) {
    extern __shared__ float sy[];                 // [128][129]
    __shared__ float rs[NN];
    __shared__ float Ds[NN];
    __shared__ float mrow[NN];
    int v = blockIdx.x;
    int rel = v >> 5, b = v & 31;
    int t = threadIdx.x;                          // 256
    if (rel == 0) {
        const float* Am = A + (size_t)b*NN*NN;
        if (t < NN) {
            float s = 0.f;
#pragma unroll 4
            for (int i = 0; i < NN; i++) s += Am[i*NN + t];
            Ds[t] = rsqrtf(s + 1e-5f);
        }
        __syncthreads();
        float* Lm = L0 + (size_t)b*NN*NN;
        for (int idx = t; idx < NN*NN; idx += 256) {
            int i = idx >> 7, j = idx & 127;
            Lm[idx] = Ds[i] * Am[idx] * Ds[j];
        }
        return;
    }
    const float* sm = g_s + (size_t)b*NN*NN;
    for (int idx = t; idx < NN*NN; idx += 256)
        sy[(idx >> 7)*129 + (idx & 127)] = sm[idx];
    if (t < NN) mrow[t] = mask[b*NN + t];
    __syncthreads();
    for (int idx = t; idx < NN*NN; idx += 256) {
        int i = idx >> 7, j = idx & 127;
        if (i < j) {
            float m = mrow[i] * mrow[j];
            float yv = 0.f;
            if (m != 0.f)
                yv = expf(0.5f * (sy[i*129 + j] + sy[j*129 + i]));
            sy[i*129 + j] = yv;
            sy[j*129 + i] = 0.f;
        } else if (i == j) {
            sy[i*129 + i] = 0.f;
        }
    }
    __syncthreads();
    if (t < NN) {
        float s = 0.f;
#pragma unroll 4
        for (int j = 0; j < NN; j++) s += sy[t*129 + j];
        rs[t] = (s == 0.f) ? 1.f : s;
    }
    __syncthreads();
    for (int idx = t; idx < NN*NN; idx += 256) {
        int i = idx >> 7, j = idx & 127;
        if (i < j) {
            float an = sy[i*129 + j] / rs[i];
            sy[i*129 + j] = an;
            sy[j*129 + i] = an;
        }
    }
    __syncthreads();
    if (t < NN) {
        float s = 0.f;
#pragma unroll 4
        for (int i = 0; i < NN; i++) s += sy[i*129 + t];
        Ds[t] = rsqrtf(s + 1e-5f);
    }
    __syncthreads();
    float* Lm = L1 + (size_t)b*NN*NN;
    for (int idx = t; idx < NN*NN; idx += 256) {
        int i = idx >> 7, j = idx & 127;
        Lm[idx] = Ds[i] * sy[i*129 + j] * Ds[j];
    }
}

// =============== GEMM config: 64-row M tiles, 8 warps ===============
template<int NT> struct Cfg {
    static constexpr int WN = (NT == 128) ? 4 : 2;   // warps along N
    static constexpr int WM = 8 / WN;                // warps along M
    static constexpr int ROWS = 64 / WM;             // rows per warp (32 or 16)
    static constexpr int MT = ROWS / 16;             // m16 tiles per warp (2 or 1)
    static constexpr int TPR = NT / 4;               // threads per B row
    static constexpr int RSTEP = 256 / TPR;          // B rows per iteration
    static constexpr int IB = 32 / RSTEP;            // B load iterations
};

// Shared GEMM core: computes acc for a 64 x NT tile.
// Aop: row-major [64+brow x K] via lda; Bop: row-major [K x NT+bcol] via ldbm.
template<int NT, bool COPY>
__device__ __forceinline__ void gemm_core(
        const float* __restrict__ Aop, int lda, int brow,
        const float* __restrict__ Bop, int ldbm, int bcol, int K,
        float* __restrict__ Copy, int wcopy,
        unsigned (*As)[36], unsigned (*Bs)[NT + 4],
        float acc[Cfg<NT>::MT][4][4]) {
    typedef Cfg<NT> G;
    int t = threadIdx.x;
    int am = t >> 3, ak = (t & 7) * 4;
    int bk = t / G::TPR, bn = (t % G::TPR) * 4;
    float4 ar[2], br[G::IB];
#pragma unroll
    for (int r = 0; r < 2; r++) ar[r] = *(const float4*)(Aop + (size_t)(brow + am + r*32)*lda + ak);
#pragma unroll
    for (int r = 0; r < G::IB; r++) br[r] = *(const float4*)(Bop + (size_t)(bk + r*G::RSTEP)*ldbm + bcol + bn);
    int warp = t >> 5, lane = t & 31;
    int warpM = (warp / G::WN) * G::ROWS, warpN = (warp % G::WN) * 32;
    int g = lane >> 2, tg = lane & 3;
    for (int k0 = 0; k0 < K; k0 += 32) {
#pragma unroll
        for (int r = 0; r < 2; r++) *(uint4*)&As[am + r*32][ak] = f2tf4(ar[r]);
#pragma unroll
        for (int r = 0; r < G::IB; r++) {
            *(uint4*)&Bs[bk + r*G::RSTEP][bn] = f2tf4(br[r]);
            if (COPY) *(float4*)(Copy + (size_t)(k0 + bk + r*G::RSTEP)*wcopy + bcol + bn) = br[r];
        }
        __syncthreads();
        if (k0 + 32 < K) {
#pragma unroll
            for (int r = 0; r < 2; r++) ar[r] = *(const float4*)(Aop + (size_t)(brow + am + r*32)*lda + k0 + 32 + ak);
#pragma unroll
            for (int r = 0; r < G::IB; r++) br[r] = *(const float4*)(Bop + (size_t)(k0 + 32 + bk + r*G::RSTEP)*ldbm + bcol + bn);
        }
#pragma unroll
        for (int ks = 0; ks < 4; ks++) {
            int kb = ks * 8;
            unsigned a[G::MT][4], bb[4][2];
#pragma unroll
            for (int mt = 0; mt < G::MT; mt++) {
                int r0 = warpM + mt*16 + g;
                a[mt][0] = As[r0][kb + tg];
                a[mt][1] = As[r0 + 8][kb + tg];
                a[mt][2] = As[r0][kb + tg + 4];
                a[mt][3] = As[r0 + 8][kb + tg + 4];
            }
#pragma unroll
            for (int nt = 0; nt < 4; nt++) {
                int c0 = warpN + nt*8 + g;
                bb[nt][0] = Bs[kb + tg][c0];
                bb[nt][1] = Bs[kb + tg + 4][c0];
            }
#pragma unroll
            for (int mt = 0; mt < G::MT; mt++)
#pragma unroll
                for (int nt = 0; nt < 4; nt++)
                    mma_tf32(acc[mt][nt], a[mt], bb[nt]);
        }
        __syncthreads();
    }
}

// =============== M = 2*L@L - I ; tiles 64x128, grid (2, 2, B) =======
__global__ __launch_bounds__(256) void k_mgemm() {
    typedef Cfg<128> G;
    __shared__ unsigned As[64][36];
    __shared__ unsigned Bs[32][132];
    int mhalf = blockIdx.x, rel = blockIdx.y, b = blockIdx.z;
    int brow = mhalf * 64;
    const float* Lm = (rel ? g_L1 : g_L0) + (size_t)b*NN*NN;
    float*       Mm = (rel ? g_M1 : g_M0) + (size_t)b*NN*NN;
    float acc[G::MT][4][4] = {};
    gemm_core<128, false>(Lm, NN, brow, Lm, NN, 0, NN, nullptr, 0, As, Bs, acc);
    int t = threadIdx.x;
    int warp = t >> 5, lane = t & 31;
    int warpM = (warp / G::WN) * G::ROWS, warpN = (warp % G::WN) * 32;
    int g = lane >> 2, tg = lane & 3;
#pragma unroll
    for (int nt = 0; nt < 4; nt++) {
        int c0 = warpN + nt*8 + tg*2;
#pragma unroll
        for (int mt = 0; mt < G::MT; mt++) {
            int r0 = brow + warpM + mt*16 + g;
            Mm[(size_t)r0*NN + c0]           = 2.f*acc[mt][nt][0] - (r0 == c0 ? 1.f : 0.f);
            Mm[(size_t)r0*NN + c0 + 1]       = 2.f*acc[mt][nt][1] - (r0 == c0 + 1 ? 1.f : 0.f);
            Mm[(size_t)(r0 + 8)*NN + c0]     = 2.f*acc[mt][nt][2] - (r0 + 8 == c0 ? 1.f : 0.f);
            Mm[(size_t)(r0 + 8)*NN + c0 + 1] = 2.f*acc[mt][nt][3] - (r0 + 8 == c0 + 1 ? 1.f : 0.f);
        }
    }
}

// ====== Chebyshev: grid.x = (colblk, mhalf); grid.y = (rel,term); T = {L,M}@X ======
template<int NT>
__global__ __launch_bounds__(256) void k_cheb(const float* __restrict__ X, int fin, int w) {
    typedef Cfg<NT> G;
    __shared__ unsigned As[64][36];
    __shared__ unsigned Bs[32][NT + 4];
    int mhalf = blockIdx.x & 1, colblk = blockIdx.x >> 1;
    int rel = blockIdx.y >> 1, term = blockIdx.y & 1;
    int b = blockIdx.z, bcol = colblk * NT, brow = mhalf * 64;
    const float* Am = (rel ? (term ? g_M1 : g_L1) : (term ? g_M0 : g_L0)) + (size_t)b*NN*NN;
    const float* Bm = X + (size_t)b*NN*fin;
    float* Cm   = g_Xcat + (size_t)b*NN*w + (size_t)(1 + term + rel*3)*fin;
    float* Copy = g_Xcat + (size_t)b*NN*w + (size_t)(rel*3)*fin;
    float acc[G::MT][4][4] = {};
    if (term == 0 && mhalf == 0)
        gemm_core<NT, true>(Am, NN, brow, Bm, fin, bcol, NN, Copy, w, As, Bs, acc);
    else
        gemm_core<NT, false>(Am, NN, brow, Bm, fin, bcol, NN, nullptr, 0, As, Bs, acc);
    int t = threadIdx.x;
    int warp = t >> 5, lane = t & 31;
    int warpM = (warp / G::WN) * G::ROWS, warpN = (warp % G::WN) * 32;
    int g = lane >> 2, tg = lane & 3;
#pragma unroll
    for (int nt = 0; nt < 4; nt++) {
        int c0 = bcol + warpN + nt*8 + tg*2;
#pragma unroll
        for (int mt = 0; mt < G::MT; mt++) {
            int r0 = brow + warpM + mt*16 + g;
            Cm[(size_t)r0*w + c0]           = acc[mt][nt][0];
            Cm[(size_t)r0*w + c0 + 1]       = acc[mt][nt][1];
            Cm[(size_t)(r0 + 8)*w + c0]     = acc[mt][nt][2];
            Cm[(size_t)(r0 + 8)*w + c0 + 1] = acc[mt][nt][3];
        }
    }
}

// ===== FC GEMM: O = relu(BN(mask * (Xcat @ W + bias))) ; tiles 64 x NT =====
template<int NT>
__global__ __launch_bounds__(256) void k_fcgemm(
        const float* __restrict__ X, const float* __restrict__ W,
        const float* __restrict__ bias, const float* __restrict__ bnm,
        const float* __restrict__ bnv, const float* __restrict__ bng,
        const float* __restrict__ bnb, const float* __restrict__ mask,
        float* __restrict__ O, int K, int Nc) {
    typedef Cfg<NT> G;
    __shared__ unsigned As[64][36];
    __shared__ unsigned Bs[32][NT + 4];
    int brow = blockIdx.y * 64;
    int bcol = blockIdx.x * NT;
    float acc[G::MT][4][4] = {};
    gemm_core<NT, false>(X, K, brow, W, Nc, bcol, K, nullptr, 0, As, Bs, acc);
    int t = threadIdx.x;
    int warp = t >> 5, lane = t & 31;
    int warpM = (warp / G::WN) * G::ROWS, warpN = (warp % G::WN) * 32;
    int g = lane >> 2, tg = lane & 3;
#pragma unroll
    for (int nt = 0; nt < 4; nt++) {
        int c0 = bcol + warpN + nt*8 + tg*2;
        float sc0 = bng[c0]     * rsqrtf(bnv[c0]     + EPS_BN);
        float sc1 = bng[c0 + 1] * rsqrtf(bnv[c0 + 1] + EPS_BN);
        float bi0 = bias[c0], bi1 = bias[c0 + 1];
        float m0 = bnm[c0], m1 = bnm[c0 + 1];
        float be0 = bnb[c0], be1 = bnb[c0 + 1];
#pragma unroll
        for (int mt = 0; mt < G::MT; mt++) {
            int r0 = brow + warpM + mt*16 + g;
            float mk0 = mask[r0], mk1 = mask[r0 + 8];
            float v;
            v = ((acc[mt][nt][0] + bi0)*mk0 - m0)*sc0 + be0;
            O[(size_t)r0*Nc + c0]         = fmaxf(v, 0.f);
            v = ((acc[mt][nt][1] + bi1)*mk0 - m1)*sc1 + be1;
            O[(size_t)r0*Nc + c0 + 1]     = fmaxf(v, 0.f);
            v = ((acc[mt][nt][2] + bi0)*mk1 - m0)*sc0 + be0;
            O[(size_t)(r0 + 8)*Nc + c0]     = fmaxf(v, 0.f);
            v = ((acc[mt][nt][3] + bi1)*mk1 - m1)*sc1 + be1;
            O[(size_t)(r0 + 8)*Nc + c0 + 1] = fmaxf(v, 0.f);
        }
    }
}

// ---------------- max-pool over nodes (4 independent chains) ----------------
__global__ void k_pool(const float* __restrict__ H) {
    int b = blockIdx.x, c = threadIdx.x;      // 512
    const float* Hb = H + (size_t)b*NN*512 + c;
    float m0 = Hb[0*512], m1 = Hb[1*512], m2 = Hb[2*512], m3 = Hb[3*512];
#pragma unroll 4
    for (int n = 4; n < NN; n += 4) {
        m0 = fmaxf(m0, Hb[(size_t)n*512]);
        m1 = fmaxf(m1, Hb[(size_t)(n + 1)*512]);
        m2 = fmaxf(m2, Hb[(size_t)(n + 2)*512]);
        m3 = fmaxf(m3, Hb[(size_t)(n + 3)*512]);
    }
    g_pool[b*512 + c] = fmaxf(fmaxf(m0, m1), fmaxf(m2, m3));
}

// ---------------- classifier ----------------
__global__ void k_fc1(const float* __restrict__ fW1, const float* __restrict__ fb1) {
    int b = blockIdx.x, t = threadIdx.x;      // 256
    __shared__ float ps[512];
    for (int i = t; i < 512; i += 256) ps[i] = g_pool[b*512 + i];
    __syncthreads();
    float acc = fb1[t];
#pragma unroll 4
    for (int k = 0; k < 512; k++) acc += ps[k] * fW1[k*NH + t];
    g_fc1[b*NH + t] = acc;
}

__global__ void k_fc2(const float* __restrict__ fW2, const float* __restrict__ fb2,
                      float* __restrict__ out) {
    int b = blockIdx.x, t = threadIdx.x;      // 32
    __shared__ float ps[NH];
    for (int i = t; i < NH; i += 32) ps[i] = g_fc1[b*NH + i];
    __syncthreads();
    if (t < OUT) {
        float acc = fb2[t];
#pragma unroll 4
        for (int k = 0; k < NH; k++) acc += ps[k] * fW2[k*OUT + t];
        out[b*OUT + t] = acc;
    }
}

// ---------------- host launch ----------------
static void* dev_ptr(const void* sym) {
    void* p = nullptr;
    cudaGetSymbolAddress(&p, sym);
    return p;
}

extern "C" void kernel_launch(void* const* d_in, const int* in_sizes, int n_in,
                              void* d_out, int out_size) {
    const float* x    = (const float*)d_in[0];
    const float* A    = (const float*)d_in[1];
    const float* mask = (const float*)d_in[2];
    const float* eW1  = (const float*)d_in[3];
    const float* eb1  = (const float*)d_in[4];
    const float* eW2  = (const float*)d_in[5];
    const float* eb2  = (const float*)d_in[6];
    const float* gW[3]  = {(const float*)d_in[7],  (const float*)d_in[13], (const float*)d_in[19]};
    const float* gb[3]  = {(const float*)d_in[8],  (const float*)d_in[14], (const float*)d_in[20]};
    const float* bng[3] = {(const float*)d_in[9],  (const float*)d_in[15], (const float*)d_in[21]};
    const float* bnb[3] = {(const float*)d_in[10], (const float*)d_in[16], (const float*)d_in[22]};
    const float* bnm[3] = {(const float*)d_in[11], (const float*)d_in[17], (const float*)d_in[23]};
    const float* bnv[3] = {(const float*)d_in[12], (const float*)d_in[18], (const float*)d_in[24]};
    const float* fW1 = (const float*)d_in[25];
    const float* fb1 = (const float*)d_in[26];
    const float* fW2 = (const float*)d_in[27];
    const float* fb2 = (const float*)d_in[28];
    float* out = (float*)d_out;

    float* p_Xcat = (float*)dev_ptr(g_Xcat);
    float* p_h0   = (float*)dev_ptr(g_h0);
    float* p_h1   = (float*)dev_ptr(g_h1);
    float* p_L0   = (float*)dev_ptr(g_L0);
    float* p_L1   = (float*)dev_ptr(g_L1);

    // edge adjacency (fused)
    k_uv<<<B*NN, HE>>>(x, eW1, eb1);
    k_score<<<B*(NN/IC), 128>>>(eW2, eb2);
    const int adjSmem = 128*129*4;
    cudaFuncSetAttribute(k_adj, cudaFuncAttributeMaxDynamicSharedMemorySize, adjSmem);
    k_adj<<<2*B, 256, adjSmem>>>(A, mask, p_L0, p_L1);

    // M = 2L^2 - I (shared by all 3 layers); 128 blocks
    k_mgemm<<<dim3(2, 2, B), 256>>>();

    const int   FIN[3]  = {128, 64, 256};
    const int   FOUT[3] = {64, 256, 512};
    const float* Xin[3] = {x, p_h0, p_h1};
    float*      Hout[3] = {p_h0, p_h1, p_h0};

    for (int li = 0; li < 3; li++) {
        int fin = FIN[li], f = FOUT[li], w = 6*fin;
        if (fin >= 128)
            k_cheb<128><<<dim3((fin/128)*2, 4, B), 256>>>(Xin[li], fin, w);
        else
            k_cheb<64><<<dim3((fin/64)*2, 4, B), 256>>>(Xin[li], fin, w);
        if (f >= 128) {
            dim3 gf(f/128, (B*NN)/64);
            k_fcgemm<128><<<gf, 256>>>(p_Xcat, gW[li], gb[li], bnm[li], bnv[li],
                                       bng[li], bnb[li], mask, Hout[li], w, f);
        } else {
            dim3 gf(f/64, (B*NN)/64);
            k_fcgemm<64><<<gf, 256>>>(p_Xcat, gW[li], gb[li], bnm[li], bnv[li],
                                      bng[li], bnb[li], mask, Hout[li], w, f);
        }
    }

    k_pool<<<B, 512>>>(p_h0);
    k_fc1<<<B, NH>>>(fW1, fb1);
    k_fc2<<<B, 32>>>(fW2, fb2, out);
}

// round 16
// speedup vs baseline: 1.0413x; 1.0413x over previous
#include <cuda_runtime.h>
#include <math.h>

#define B 32
#define NN 128
#define C 128
#define HE 64
#define NH 256
#define OUT 10
#define EPS_BN 1e-5f

// ---------------- scratch (device globals; no allocs allowed) ----------------
__device__ float g_u[B*NN*HE];
__device__ float g_v[B*NN*HE];
__device__ float g_s[B*NN*NN];
__device__ float g_L0[B*NN*NN];
__device__ float g_L1[B*NN*NN];
__device__ float g_M0[B*NN*NN];
__device__ float g_M1[B*NN*NN];
__device__ float g_Xcat[B*NN*1280];   // max 5*256 wide
__device__ float g_h0[B*NN*512];
__device__ float g_h1[B*NN*512];
__device__ float g_Wc0[5*128*64];
__device__ float g_Wc1[5*64*256];
__device__ float g_Wc2[5*256*512];

__device__ __forceinline__ unsigned f2tf(float f) {
    unsigned u;
    asm("cvt.rna.tf32.f32 %0, %1;" : "=r"(u) : "f"(f));
    return u;
}
__device__ __forceinline__ uint4 f2tf4(float4 v) {
    uint4 s; s.x = f2tf(v.x); s.y = f2tf(v.y); s.z = f2tf(v.z); s.w = f2tf(v.w);
    return s;
}

__device__ __forceinline__ void mma_tf32(float c[4], const unsigned a[4], const unsigned b[2]) {
    asm volatile(
        "mma.sync.aligned.m16n8k8.row.col.f32.tf32.tf32.f32 "
        "{%0,%1,%2,%3}, {%4,%5,%6,%7}, {%8,%9}, {%0,%1,%2,%3};"
        : "+f"(c[0]), "+f"(c[1]), "+f"(c[2]), "+f"(c[3])
        : "r"(a[0]), "r"(a[1]), "r"(a[2]), "r"(a[3]), "r"(b[0]), "r"(b[1]));
}

// ------------- fold weights: Wc rows [W0+W3, W1, W2, W4, W5] -------------
__global__ void k_fold(const float* __restrict__ W, float* __restrict__ Wc,
                       int fin, int f) {
    int total = 5*fin*f;
    for (int idx = blockIdx.x*blockDim.x + threadIdx.x; idx < total;
         idx += gridDim.x*blockDim.x) {
        int r = idx / f, c = idx - r*f;
        float v;
        if (r < fin)           v = W[r*f + c] + W[(3*fin + r)*f + c];
        else if (r < 3*fin)    v = W[r*f + c];
        else                   v = W[(fin + r)*f + c];
        Wc[idx] = v;
    }
}

// ---------------- edge MLP: u = x@eW1[:C]+eb1, v = x@eW1[C:] ----------------
__global__ void k_uv(const float* __restrict__ x, const float* __restrict__ eW1,
                     const float* __restrict__ eb1) {
    int row = blockIdx.x;            // b*NN + n
    __shared__ float xs[C];
    for (int c = threadIdx.x; c < C; c += blockDim.x) xs[c] = x[row*C + c];
    __syncthreads();
    int t = threadIdx.x;             // 64 threads = HE
    float u = 0.f, v = 0.f;
#pragma unroll 4
    for (int c = 0; c < C; c++) {
        float xv = xs[c];
        u += xv * eW1[c*HE + t];
        v += xv * eW1[(C + c)*HE + t];
    }
    g_u[row*HE + t] = u + eb1[t];
    g_v[row*HE + t] = v;
}

// ---------------- edge scores s[b,i,j] ----------------
#define IC 16
__global__ void k_score(const float* __restrict__ eW2, const float* __restrict__ eb2) {
    int b  = blockIdx.x / (NN / IC);
    int i0 = (blockIdx.x % (NN / IC)) * IC;
    __shared__ float vs[NN*(HE + 1)];
    __shared__ float us[IC*HE];
    __shared__ float w2[HE];
    int tid = threadIdx.x;           // 128
    for (int idx = tid; idx < NN*HE; idx += 128) {
        int j = idx / HE, h = idx % HE;
        vs[j*(HE + 1) + h] = g_v[(b*NN + j)*HE + h];
    }
    for (int idx = tid; idx < IC*HE; idx += 128)
        us[idx] = g_u[(b*NN + i0)*HE + idx];
    if (tid < HE) w2[tid] = eW2[tid];
    __syncthreads();
    float e2 = eb2[0];
    int j = tid;
    for (int ii = 0; ii < IC; ii++) {
        float acc = e2;
#pragma unroll 8
        for (int h = 0; h < HE; h++) {
            float t = us[ii*HE + h] + vs[j*(HE + 1) + h];
            acc += w2[h] * fmaxf(t, 0.f);
        }
        g_s[(b*NN + i0 + ii)*NN + j] = acc;
    }
}

// ====== fused adjacency: blocks 0..31 -> L0 from A; 32..63 -> L1 from s ======
__global__ void k_adj(const float* __restrict__ A, const float* __restrict__ mask,
                      float* __restrict__ L0, float* __restrict__ L1) {
    extern __shared__ float sy[];                 // [128][129]
    __shared__ float rs[NN];
    __shared__ float Ds[NN];
    __shared__ float mrow[NN];
    int v = blockIdx.x;
    int rel = v >> 5, b = v & 31;
    int t = threadIdx.x;                          // 256
    if (rel == 0) {
        const float* Am = A + (size_t)b*NN*NN;
        if (t < NN) {
            float s = 0.f;
#pragma unroll 4
            for (int i = 0; i < NN; i++) s += Am[i*NN + t];
            Ds[t] = rsqrtf(s + 1e-5f);
        }
        __syncthreads();
        float* Lm = L0 + (size_t)b*NN*NN;
        for (int idx = t; idx < NN*NN; idx += 256) {
            int i = idx >> 7, j = idx & 127;
            Lm[idx] = Ds[i] * Am[idx] * Ds[j];
        }
        return;
    }
    const float* sm = g_s + (size_t)b*NN*NN;
    for (int idx = t; idx < NN*NN; idx += 256)
        sy[(idx >> 7)*129 + (idx & 127)] = sm[idx];
    if (t < NN) mrow[t] = mask[b*NN + t];
    __syncthreads();
    for (int idx = t; idx < NN*NN; idx += 256) {
        int i = idx >> 7, j = idx & 127;
        if (i < j) {
            float m = mrow[i] * mrow[j];
            float yv = 0.f;
            if (m != 0.f)
                yv = expf(0.5f * (sy[i*129 + j] + sy[j*129 + i]));
            sy[i*129 + j] = yv;
            sy[j*129 + i] = 0.f;
        } else if (i == j) {
            sy[i*129 + i] = 0.f;
        }
    }
    __syncthreads();
    if (t < NN) {
        float s = 0.f;
#pragma unroll 4
        for (int j = 0; j < NN; j++) s += sy[t*129 + j];
        rs[t] = (s == 0.f) ? 1.f : s;
    }
    __syncthreads();
    for (int idx = t; idx < NN*NN; idx += 256) {
        int i = idx >> 7, j = idx & 127;
        if (i < j) {
            float an = sy[i*129 + j] / rs[i];
            sy[i*129 + j] = an;
            sy[j*129 + i] = an;
        }
    }
    __syncthreads();
    if (t < NN) {
        float s = 0.f;
#pragma unroll 4
        for (int i = 0; i < NN; i++) s += sy[i*129 + t];
        Ds[t] = rsqrtf(s + 1e-5f);
    }
    __syncthreads();
    float* Lm = L1 + (size_t)b*NN*NN;
    for (int idx = t; idx < NN*NN; idx += 256) {
        int i = idx >> 7, j = idx & 127;
        Lm[idx] = Ds[i] * sy[i*129 + j] * Ds[j];
    }
}

// =============== GEMM config: 64-row M tiles, 8 warps ===============
template<int NT> struct Cfg {
    static constexpr int WN = (NT == 128) ? 4 : 2;   // warps along N
    static constexpr int WM = 8 / WN;                // warps along M
    static constexpr int ROWS = 64 / WM;             // rows per warp (32 or 16)
    static constexpr int MT = ROWS / 16;             // m16 tiles per warp (2 or 1)
    static constexpr int TPR = NT / 4;               // threads per B row
    static constexpr int RSTEP = 256 / TPR;          // B rows per iteration
    static constexpr int IB = 32 / RSTEP;            // B load iterations
};

// Shared GEMM core: computes acc for a 64 x NT tile.
template<int NT, bool COPY>
__device__ __forceinline__ void gemm_core(
        const float* __restrict__ Aop, int lda, int brow,
        const float* __restrict__ Bop, int ldbm, int bcol, int K,
        float* __restrict__ Copy, int wcopy,
        unsigned (*As)[36], unsigned (*Bs)[NT + 4],
        float acc[Cfg<NT>::MT][4][4]) {
    typedef Cfg<NT> G;
    int t = threadIdx.x;
    int am = t >> 3, ak = (t & 7) * 4;
    int bk = t / G::TPR, bn = (t % G::TPR) * 4;
    float4 ar[2], br[G::IB];
#pragma unroll
    for (int r = 0; r < 2; r++) ar[r] = *(const float4*)(Aop + (size_t)(brow + am + r*32)*lda + ak);
#pragma unroll
    for (int r = 0; r < G::IB; r++) br[r] = *(const float4*)(Bop + (size_t)(bk + r*G::RSTEP)*ldbm + bcol + bn);
    int warp = t >> 5, lane = t & 31;
    int warpM = (warp / G::WN) * G::ROWS, warpN = (warp % G::WN) * 32;
    int g = lane >> 2, tg = lane & 3;
    for (int k0 = 0; k0 < K; k0 += 32) {
#pragma unroll
        for (int r = 0; r < 2; r++) *(uint4*)&As[am + r*32][ak] = f2tf4(ar[r]);
#pragma unroll
        for (int r = 0; r < G::IB; r++) {
            *(uint4*)&Bs[bk + r*G::RSTEP][bn] = f2tf4(br[r]);
            if (COPY) *(float4*)(Copy + (size_t)(k0 + bk + r*G::RSTEP)*wcopy + bcol + bn) = br[r];
        }
        __syncthreads();
        if (k0 + 32 < K) {
#pragma unroll
            for (int r = 0; r < 2; r++) ar[r] = *(const float4*)(Aop + (size_t)(brow + am + r*32)*lda + k0 + 32 + ak);
#pragma unroll
            for (int r = 0; r < G::IB; r++) br[r] = *(const float4*)(Bop + (size_t)(k0 + 32 + bk + r*G::RSTEP)*ldbm + bcol + bn);
        }
#pragma unroll
        for (int ks = 0; ks < 4; ks++) {
            int kb = ks * 8;
            unsigned a[G::MT][4], bb[4][2];
#pragma unroll
            for (int mt = 0; mt < G::MT; mt++) {
                int r0 = warpM + mt*16 + g;
                a[mt][0] = As[r0][kb + tg];
                a[mt][1] = As[r0 + 8][kb + tg];
                a[mt][2] = As[r0][kb + tg + 4];
                a[mt][3] = As[r0 + 8][kb + tg + 4];
            }
#pragma unroll
            for (int nt = 0; nt < 4; nt++) {
                int c0 = warpN + nt*8 + g;
                bb[nt][0] = Bs[kb + tg][c0];
                bb[nt][1] = Bs[kb + tg + 4][c0];
            }
#pragma unroll
            for (int mt = 0; mt < G::MT; mt++)
#pragma unroll
                for (int nt = 0; nt < 4; nt++)
                    mma_tf32(acc[mt][nt], a[mt], bb[nt]);
        }
        __syncthreads();
    }
}

// =============== M = 2*L@L - I ; tiles 64x128, grid (2, 2, B) =======
__global__ __launch_bounds__(256) void k_mgemm() {
    typedef Cfg<128> G;
    __shared__ unsigned As[64][36];
    __shared__ unsigned Bs[32][132];
    int mhalf = blockIdx.x, rel = blockIdx.y, b = blockIdx.z;
    int brow = mhalf * 64;
    const float* Lm = (rel ? g_L1 : g_L0) + (size_t)b*NN*NN;
    float*       Mm = (rel ? g_M1 : g_M0) + (size_t)b*NN*NN;
    float acc[G::MT][4][4] = {};
    gemm_core<128, false>(Lm, NN, brow, Lm, NN, 0, NN, nullptr, 0, As, Bs, acc);
    int t = threadIdx.x;
    int warp = t >> 5, lane = t & 31;
    int warpM = (warp / G::WN) * G::ROWS, warpN = (warp % G::WN) * 32;
    int g = lane >> 2, tg = lane & 3;
#pragma unroll
    for (int nt = 0; nt < 4; nt++) {
        int c0 = warpN + nt*8 + tg*2;
#pragma unroll
        for (int mt = 0; mt < G::MT; mt++) {
            int r0 = brow + warpM + mt*16 + g;
            Mm[(size_t)r0*NN + c0]           = 2.f*acc[mt][nt][0] - (r0 == c0 ? 1.f : 0.f);
            Mm[(size_t)r0*NN + c0 + 1]       = 2.f*acc[mt][nt][1] - (r0 == c0 + 1 ? 1.f : 0.f);
            Mm[(size_t)(r0 + 8)*NN + c0]     = 2.f*acc[mt][nt][2] - (r0 + 8 == c0 ? 1.f : 0.f);
            Mm[(size_t)(r0 + 8)*NN + c0 + 1] = 2.f*acc[mt][nt][3] - (r0 + 8 == c0 + 1 ? 1.f : 0.f);
        }
    }
}

// ====== Chebyshev: Xcat = [X, L0X, M0X, L1X, M1X]; w = 5*fin ======
template<int NT>
__global__ __launch_bounds__(256) void k_cheb(const float* __restrict__ X, int fin, int w) {
    typedef Cfg<NT> G;
    __shared__ unsigned As[64][36];
    __shared__ unsigned Bs[32][NT + 4];
    int mhalf = blockIdx.x & 1, colblk = blockIdx.x >> 1;
    int rel = blockIdx.y >> 1, term = blockIdx.y & 1;
    int b = blockIdx.z, bcol = colblk * NT, brow = mhalf * 64;
    const float* Am = (rel ? (term ? g_M1 : g_L1) : (term ? g_M0 : g_L0)) + (size_t)b*NN*NN;
    const float* Bm = X + (size_t)b*NN*fin;
    int slot = rel ? (3 + term) : (1 + term);
    float* Cm   = g_Xcat + (size_t)b*NN*w + (size_t)slot*fin;
    float* Copy = g_Xcat + (size_t)b*NN*w;
    float acc[G::MT][4][4] = {};
    if (rel == 0 && term == 0 && mhalf == 0)
        gemm_core<NT, true>(Am, NN, brow, Bm, fin, bcol, NN, Copy, w, As, Bs, acc);
    else
        gemm_core<NT, false>(Am, NN, brow, Bm, fin, bcol, NN, nullptr, 0, As, Bs, acc);
    int t = threadIdx.x;
    int warp = t >> 5, lane = t & 31;
    int warpM = (warp / G::WN) * G::ROWS, warpN = (warp % G::WN) * 32;
    int g = lane >> 2, tg = lane & 3;
#pragma unroll
    for (int nt = 0; nt < 4; nt++) {
        int c0 = bcol + warpN + nt*8 + tg*2;
#pragma unroll
        for (int mt = 0; mt < G::MT; mt++) {
            int r0 = brow + warpM + mt*16 + g;
            Cm[(size_t)r0*w + c0]           = acc[mt][nt][0];
            Cm[(size_t)r0*w + c0 + 1]       = acc[mt][nt][1];
            Cm[(size_t)(r0 + 8)*w + c0]     = acc[mt][nt][2];
            Cm[(size_t)(r0 + 8)*w + c0 + 1] = acc[mt][nt][3];
        }
    }
}

// ===== FC GEMM: O = relu(BN(mask * (Xcat @ Wc + bias))) ; tiles 64 x NT =====
template<int NT>
__global__ __launch_bounds__(256) void k_fcgemm(
        const float* __restrict__ X, const float* __restrict__ W,
        const float* __restrict__ bias, const float* __restrict__ bnm,
        const float* __restrict__ bnv, const float* __restrict__ bng,
        const float* __restrict__ bnb, const float* __restrict__ mask,
        float* __restrict__ O, int K, int Nc) {
    typedef Cfg<NT> G;
    __shared__ unsigned As[64][36];
    __shared__ unsigned Bs[32][NT + 4];
    int brow = blockIdx.y * 64;
    int bcol = blockIdx.x * NT;
    float acc[G::MT][4][4] = {};
    gemm_core<NT, false>(X, K, brow, W, Nc, bcol, K, nullptr, 0, As, Bs, acc);
    int t = threadIdx.x;
    int warp = t >> 5, lane = t & 31;
    int warpM = (warp / G::WN) * G::ROWS, warpN = (warp % G::WN) * 32;
    int g = lane >> 2, tg = lane & 3;
#pragma unroll
    for (int nt = 0; nt < 4; nt++) {
        int c0 = bcol + warpN + nt*8 + tg*2;
        float sc0 = bng[c0]     * rsqrtf(bnv[c0]     + EPS_BN);
        float sc1 = bng[c0 + 1] * rsqrtf(bnv[c0 + 1] + EPS_BN);
        float bi0 = bias[c0], bi1 = bias[c0 + 1];
        float m0 = bnm[c0], m1 = bnm[c0 + 1];
        float be0 = bnb[c0], be1 = bnb[c0 + 1];
#pragma unroll
        for (int mt = 0; mt < G::MT; mt++) {
            int r0 = brow + warpM + mt*16 + g;
            float mk0 = mask[r0], mk1 = mask[r0 + 8];
            float v;
            v = ((acc[mt][nt][0] + bi0)*mk0 - m0)*sc0 + be0;
            O[(size_t)r0*Nc + c0]         = fmaxf(v, 0.f);
            v = ((acc[mt][nt][1] + bi1)*mk0 - m1)*sc1 + be1;
            O[(size_t)r0*Nc + c0 + 1]     = fmaxf(v, 0.f);
            v = ((acc[mt][nt][2] + bi0)*mk1 - m0)*sc0 + be0;
            O[(size_t)(r0 + 8)*Nc + c0]     = fmaxf(v, 0.f);
            v = ((acc[mt][nt][3] + bi1)*mk1 - m1)*sc1 + be1;
            O[(size_t)(r0 + 8)*Nc + c0 + 1] = fmaxf(v, 0.f);
        }
    }
}

// -------- fused tail: max-pool over nodes -> fc1 -> fc2 ; grid = B --------
__global__ void k_tail(const float* __restrict__ H,
                       const float* __restrict__ fW1, const float* __restrict__ fb1,
                       const float* __restrict__ fW2, const float* __restrict__ fb2,
                       float* __restrict__ out) {
    __shared__ float ps[512];
    __shared__ float h1[NH];
    int b = blockIdx.x, t = threadIdx.x;      // 256
    for (int c = t; c < 512; c += 256) {
        const float* Hb = H + (size_t)b*NN*512 + c;
        float m0 = Hb[0*512], m1 = Hb[1*512], m2 = Hb[2*512], m3 = Hb[3*512];
#pragma unroll 4
        for (int n = 4; n < NN; n += 4) {
            m0 = fmaxf(m0, Hb[(size_t)n*512]);
            m1 = fmaxf(m1, Hb[(size_t)(n + 1)*512]);
            m2 = fmaxf(m2, Hb[(size_t)(n + 2)*512]);
            m3 = fmaxf(m3, Hb[(size_t)(n + 3)*512]);
        }
        ps[c] = fmaxf(fmaxf(m0, m1), fmaxf(m2, m3));
    }
    __syncthreads();
    float acc = fb1[t];
#pragma unroll 4
    for (int k = 0; k < 512; k++) acc += ps[k] * fW1[k*NH + t];
    h1[t] = acc;
    __syncthreads();
    if (t < OUT) {
        float a2 = fb2[t];
#pragma unroll 4
        for (int k = 0; k < NH; k++) a2 += h1[k] * fW2[k*OUT + t];
        out[b*OUT + t] = a2;
    }
}

// ---------------- host launch ----------------
static void* dev_ptr(const void* sym) {
    void* p = nullptr;
    cudaGetSymbolAddress(&p, sym);
    return p;
}

extern "C" void kernel_launch(void* const* d_in, const int* in_sizes, int n_in,
                              void* d_out, int out_size) {
    const float* x    = (const float*)d_in[0];
    const float* A    = (const float*)d_in[1];
    const float* mask = (const float*)d_in[2];
    const float* eW1  = (const float*)d_in[3];
    const float* eb1  = (const float*)d_in[4];
    const float* eW2  = (const float*)d_in[5];
    const float* eb2  = (const float*)d_in[6];
    const float* gW[3]  = {(const float*)d_in[7],  (const float*)d_in[13], (const float*)d_in[19]};
    const float* gb[3]  = {(const float*)d_in[8],  (const float*)d_in[14], (const float*)d_in[20]};
    const float* bng[3] = {(const float*)d_in[9],  (const float*)d_in[15], (const float*)d_in[21]};
    const float* bnb[3] = {(const float*)d_in[10], (const float*)d_in[16], (const float*)d_in[22]};
    const float* bnm[3] = {(const float*)d_in[11], (const float*)d_in[17], (const float*)d_in[23]};
    const float* bnv[3] = {(const float*)d_in[12], (const float*)d_in[18], (const float*)d_in[24]};
    const float* fW1 = (const float*)d_in[25];
    const float* fb1 = (const float*)d_in[26];
    const float* fW2 = (const float*)d_in[27];
    const float* fb2 = (const float*)d_in[28];
    float* out = (float*)d_out;

    float* p_Xcat = (float*)dev_ptr(g_Xcat);
    float* p_h0   = (float*)dev_ptr(g_h0);
    float* p_h1   = (float*)dev_ptr(g_h1);
    float* p_L0   = (float*)dev_ptr(g_L0);
    float* p_L1   = (float*)dev_ptr(g_L1);
    float* p_Wc[3] = {(float*)dev_ptr(g_Wc0), (float*)dev_ptr(g_Wc1), (float*)dev_ptr(g_Wc2)};

    // fold FC weights (independent of everything; overlaps edge pipeline)
    k_fold<<<160, 256>>>(gW[0], p_Wc[0], 128, 64);
    k_fold<<<320, 256>>>(gW[1], p_Wc[1], 64, 256);
    k_fold<<<1280, 256>>>(gW[2], p_Wc[2], 256, 512);

    // edge adjacency (fused)
    k_uv<<<B*NN, HE>>>(x, eW1, eb1);
    k_score<<<B*(NN/IC), 128>>>(eW2, eb2);
    const int adjSmem = 128*129*4;
    cudaFuncSetAttribute(k_adj, cudaFuncAttributeMaxDynamicSharedMemorySize, adjSmem);
    k_adj<<<2*B, 256, adjSmem>>>(A, mask, p_L0, p_L1);

    // M = 2L^2 - I (shared by all 3 layers)
    k_mgemm<<<dim3(2, 2, B), 256>>>();

    const int   FIN[3]  = {128, 64, 256};
    const int   FOUT[3] = {64, 256, 512};
    const float* Xin[3] = {x, p_h0, p_h1};
    float*      Hout[3] = {p_h0, p_h1, p_h0};

    for (int li = 0; li < 3; li++) {
        int fin = FIN[li], f = FOUT[li], w = 5*fin;
        if (fin >= 128)
            k_cheb<128><<<dim3((fin/128)*2, 4, B), 256>>>(Xin[li], fin, w);
        else
            k_cheb<64><<<dim3((fin/64)*2, 4, B), 256>>>(Xin[li], fin, w);
        if (f >= 128) {
            dim3 gf(f/128, (B*NN)/64);
            k_fcgemm<128><<<gf, 256>>>(p_Xcat, p_Wc[li], gb[li], bnm[li], bnv[li],
                                       bng[li], bnb[li], mask, Hout[li], w, f);
        } else {
            dim3 gf(f/64, (B*NN)/64);
            k_fcgemm<64><<<gf, 256>>>(p_Xcat, p_Wc[li], gb[li], bnm[li], bnv[li],
                                      bng[li], bnb[li], mask, Hout[li], w, f);
        }
    }

    k_tail<<<B, 256>>>(p_h0, fW1, fb1, fW2, fb2, out);
}